// round 1
// baseline (speedup 1.0000x reference)
#include <cuda_runtime.h>
#include <math.h>

// Problem constants (from reference setup_inputs)
#define T_TOK 4096        // B*S
#define H_DIM 2048
#define E_NUM 8
#define I_DIM 768
#define KSEL  2
#define N1    (2*I_DIM)   // 1536
#define ROWS_TOTAL (T_TOK*KSEL)
#define AUX_COEF 0.001f

// ---------------- scratch (static device globals; no allocation) -------------
__device__ float g_gu[(size_t)ROWS_TOTAL * N1];       // gate_up output (50 MB)
__device__ float g_inter[(size_t)ROWS_TOTAL * I_DIM]; // silu(gate)*up   (25 MB)
__device__ float g_y[(size_t)ROWS_TOTAL * H_DIM];     // weighted expert out, (t,k)-addressed (67 MB)
__device__ int   g_sel[T_TOK * KSEL];
__device__ float g_wt[T_TOK * KSEL];
__device__ int   g_counts[E_NUM];
__device__ int   g_ofs[E_NUM];
__device__ int   g_cursor[E_NUM];
__device__ int   g_rows_tok[ROWS_TOTAL];
__device__ int   g_rows_slot[ROWS_TOTAL];
__device__ float g_rows_w[ROWS_TOTAL];
__device__ float g_prob_sum[E_NUM];
__device__ float g_dummy[T_TOK * E_NUM + 8];          // fallback sink if out layout smaller

// ---------------- init ----------------
__global__ void init_kernel() {
    int i = threadIdx.x;
    if (i < E_NUM) { g_counts[i] = 0; g_prob_sum[i] = 0.f; }
}

// ---------------- router: logits, softmax, top-2, aux stats -----------------
__global__ void router_kernel(const float* __restrict__ x,
                              const float* __restrict__ gw,
                              float* __restrict__ logits_out) {
    const int t = blockIdx.x;
    const float* xr = x + (size_t)t * H_DIM;
    float acc[E_NUM];
#pragma unroll
    for (int e = 0; e < E_NUM; e++) acc[e] = 0.f;

    for (int h = threadIdx.x; h < H_DIM; h += blockDim.x) {
        float xv = xr[h];
        const float4 g0 = *(const float4*)(gw + (size_t)h * E_NUM);
        const float4 g1 = *(const float4*)(gw + (size_t)h * E_NUM + 4);
        acc[0] += xv * g0.x; acc[1] += xv * g0.y; acc[2] += xv * g0.z; acc[3] += xv * g0.w;
        acc[4] += xv * g1.x; acc[5] += xv * g1.y; acc[6] += xv * g1.z; acc[7] += xv * g1.w;
    }
#pragma unroll
    for (int e = 0; e < E_NUM; e++)
#pragma unroll
        for (int o = 16; o; o >>= 1) acc[e] += __shfl_xor_sync(0xffffffffu, acc[e], o);

    __shared__ float red[E_NUM][8];
    int warp = threadIdx.x >> 5, lane = threadIdx.x & 31;
    if (lane == 0)
#pragma unroll
        for (int e = 0; e < E_NUM; e++) red[e][warp] = acc[e];
    __syncthreads();

    if (threadIdx.x == 0) {
        float lg[E_NUM];
#pragma unroll
        for (int e = 0; e < E_NUM; e++) {
            float s = 0.f;
#pragma unroll
            for (int w = 0; w < 8; w++) s += red[e][w];
            lg[e] = s;
        }
        // raw logits out
        if (logits_out)
#pragma unroll
            for (int e = 0; e < E_NUM; e++) logits_out[(size_t)t * E_NUM + e] = lg[e];
        // softmax
        float mx = lg[0];
#pragma unroll
        for (int e = 1; e < E_NUM; e++) mx = fmaxf(mx, lg[e]);
        float p[E_NUM], s = 0.f;
#pragma unroll
        for (int e = 0; e < E_NUM; e++) { p[e] = expf(lg[e] - mx); s += p[e]; }
        float inv = 1.f / s;
#pragma unroll
        for (int e = 0; e < E_NUM; e++) { p[e] *= inv; atomicAdd(&g_prob_sum[e], p[e]); }
        // top-K (K=KSEL) by selection; first-index-on-tie like jax
        bool used[E_NUM];
#pragma unroll
        for (int e = 0; e < E_NUM; e++) used[e] = false;
        int   si[KSEL]; float sp[KSEL]; float wsum = 0.f;
#pragma unroll
        for (int k = 0; k < KSEL; k++) {
            int bi = -1; float bv = -1.f;
#pragma unroll
            for (int e = 0; e < E_NUM; e++)
                if (!used[e] && p[e] > bv) { bv = p[e]; bi = e; }
            used[bi] = true; si[k] = bi; sp[k] = bv; wsum += bv;
        }
        float winv = 1.f / wsum;
#pragma unroll
        for (int k = 0; k < KSEL; k++) {
            g_sel[t * KSEL + k] = si[k];
            g_wt[t * KSEL + k]  = sp[k] * winv;
            atomicAdd(&g_counts[si[k]], 1);
        }
    }
}

// ---------------- offsets (exclusive prefix over 8 counts) ------------------
__global__ void offsets_kernel() {
    if (threadIdx.x == 0) {
        int run = 0;
        for (int e = 0; e < E_NUM; e++) {
            g_ofs[e] = run; g_cursor[e] = run; run += g_counts[e];
        }
    }
}

// ---------------- scatter tokens into per-expert row lists ------------------
__global__ void scatter_kernel() {
    int i = blockIdx.x * blockDim.x + threadIdx.x;
    if (i >= ROWS_TOTAL) return;
    int e = g_sel[i];
    int p = atomicAdd(&g_cursor[e], 1);
    g_rows_tok[p]  = i / KSEL;
    g_rows_slot[p] = i % KSEL;
    g_rows_w[p]    = g_wt[i];
}

// ---------------- tiled SGEMM (NT), gathered-A, per-expert ------------------
// MODE 1: A = x[g_rows_tok[r]] (KDIM=H), B = gate_up_proj[e], C -> g_gu
// MODE 2: A = g_inter[r]       (KDIM=I), B = down_proj[e],    C*w -> g_y[(t*K+s)]
template<int KDIM, int NDIM, int MODE>
__global__ void expert_gemm(const float* __restrict__ x,
                            const float* __restrict__ w) {
    const int e   = blockIdx.z;
    const int cnt = g_counts[e];
    const int m0  = blockIdx.x * 128;
    if (m0 >= cnt) return;
    const int n0  = blockIdx.y * 128;
    const int ofs = g_ofs[e];

    __shared__ float As[8][132];
    __shared__ float Bs[8][132];

    const int tid = threadIdx.x;
    const int am  = tid >> 1;            // 0..127 (load row within tile)
    const int ko  = (tid & 1) * 4;       // 0 or 4
    const int lm  = m0 + am;
    const bool valid = lm < cnt;
    const int grow = ofs + (valid ? lm : 0);

    const float* arow;
    if (MODE == 1) arow = x + (size_t)g_rows_tok[grow] * H_DIM;
    else           arow = g_inter + (size_t)grow * I_DIM;
    const float* brow = w + (size_t)e * NDIM * KDIM + (size_t)(n0 + am) * KDIM;

    float acc[8][8];
#pragma unroll
    for (int i = 0; i < 8; i++)
#pragma unroll
        for (int j = 0; j < 8; j++) acc[i][j] = 0.f;

    const int ry = (tid >> 4) * 8;
    const int cx = (tid & 15) * 8;

    for (int kt = 0; kt < KDIM; kt += 8) {
        float4 av = valid ? *(const float4*)(arow + kt + ko) : make_float4(0.f, 0.f, 0.f, 0.f);
        float4 bv = *(const float4*)(brow + kt + ko);
        __syncthreads();
        As[ko + 0][am] = av.x; As[ko + 1][am] = av.y; As[ko + 2][am] = av.z; As[ko + 3][am] = av.w;
        Bs[ko + 0][am] = bv.x; Bs[ko + 1][am] = bv.y; Bs[ko + 2][am] = bv.z; Bs[ko + 3][am] = bv.w;
        __syncthreads();
#pragma unroll
        for (int kk = 0; kk < 8; kk++) {
            float a[8], b[8];
            *(float4*)(a)     = *(const float4*)&As[kk][ry];
            *(float4*)(a + 4) = *(const float4*)&As[kk][ry + 4];
            *(float4*)(b)     = *(const float4*)&Bs[kk][cx];
            *(float4*)(b + 4) = *(const float4*)&Bs[kk][cx + 4];
#pragma unroll
            for (int i = 0; i < 8; i++)
#pragma unroll
                for (int j = 0; j < 8; j++) acc[i][j] += a[i] * b[j];
        }
    }

    if (MODE == 1) {
#pragma unroll
        for (int i = 0; i < 8; i++) {
            int m = m0 + ry + i;
            if (m < cnt) {
                float* o = g_gu + (size_t)(ofs + m) * N1 + n0 + cx;
                *(float4*)(o)     = *(float4*)&acc[i][0];
                *(float4*)(o + 4) = *(float4*)&acc[i][4];
            }
        }
    } else {
#pragma unroll
        for (int i = 0; i < 8; i++) {
            int m = m0 + ry + i;
            if (m < cnt) {
                int r = ofs + m;
                float wgt = g_rows_w[r];
                int t = g_rows_tok[r], s = g_rows_slot[r];
                float* o = g_y + ((size_t)t * KSEL + s) * H_DIM + n0 + cx;
                float4 v0, v1;
                v0.x = acc[i][0] * wgt; v0.y = acc[i][1] * wgt; v0.z = acc[i][2] * wgt; v0.w = acc[i][3] * wgt;
                v1.x = acc[i][4] * wgt; v1.y = acc[i][5] * wgt; v1.z = acc[i][6] * wgt; v1.w = acc[i][7] * wgt;
                *(float4*)(o)     = v0;
                *(float4*)(o + 4) = v1;
            }
        }
    }
}

// ---------------- silu(gate) * up -------------------------------------------
__global__ void silu_kernel() {
    int i = blockIdx.x * blockDim.x + threadIdx.x;   // over ROWS_TOTAL * I_DIM
    if (i >= ROWS_TOTAL * I_DIM) return;
    int r = i / I_DIM, c = i - r * I_DIM;
    float g = g_gu[(size_t)r * N1 + c];
    float u = g_gu[(size_t)r * N1 + I_DIM + c];
    g_inter[i] = (g / (1.f + expf(-g))) * u;
}

// ---------------- combine the K weighted expert outputs ---------------------
__global__ void combine_kernel(float* __restrict__ out) {
    int i = blockIdx.x * blockDim.x + threadIdx.x;   // over T*H/4
    if (i >= T_TOK * H_DIM / 4) return;
    const int nv = H_DIM / 4;
    int t = i / nv, n = i - t * nv;
    const float4* y = (const float4*)g_y;
    float4 s = y[((size_t)t * KSEL + 0) * nv + n];
#pragma unroll
    for (int k = 1; k < KSEL; k++) {
        float4 v = y[((size_t)t * KSEL + k) * nv + n];
        s.x += v.x; s.y += v.y; s.z += v.z; s.w += v.w;
    }
    ((float4*)out)[i] = s;
}

// ---------------- aux loss ---------------------------------------------------
__global__ void aux_kernel(float* __restrict__ aux_out) {
    if (threadIdx.x == 0) {
        float aux = 0.f;
        float invT = 1.f / (float)T_TOK;
        for (int e = 0; e < E_NUM; e++)
            aux += (g_prob_sum[e] * invT) * ((float)g_counts[e] * invT);
        aux *= (float)E_NUM * AUX_COEF;
        aux_out[0] = aux;
    }
}

// ---------------- launch -----------------------------------------------------
extern "C" void kernel_launch(void* const* d_in, const int* in_sizes, int n_in,
                              void* d_out, int out_size) {
    const float* x   = (const float*)d_in[0];
    const float* gw  = (const float*)d_in[1];
    const float* gup = (const float*)d_in[2];
    const float* dwn = (const float*)d_in[3];
    float* out = (float*)d_out;

    const long long need_logits = (long long)T_TOK * H_DIM + (long long)T_TOK * E_NUM;
    const bool has_logits = (long long)out_size >= need_logits;
    const bool has_aux    = (long long)out_size >= need_logits + 1;

    float* logits = nullptr;
    float* auxp   = nullptr;
    if (has_logits) logits = out + (size_t)T_TOK * H_DIM;
    if (has_aux)    auxp   = logits + (size_t)T_TOK * E_NUM;

    init_kernel<<<1, 32>>>();
    router_kernel<<<T_TOK, 256>>>(x, gw, logits);
    offsets_kernel<<<1, 32>>>();
    scatter_kernel<<<(ROWS_TOTAL + 255) / 256, 256>>>();

    // GEMM1: rows x H -> rows x 2I  (max rows per expert = T_TOK -> 32 m-tiles)
    expert_gemm<H_DIM, N1, 1><<<dim3(32, N1 / 128, E_NUM), 256>>>(x, gup);
    silu_kernel<<<(ROWS_TOTAL * I_DIM + 255) / 256, 256>>>();
    // GEMM2: rows x I -> rows x H, scaled, scattered to (t,k) slots
    expert_gemm<I_DIM, H_DIM, 2><<<dim3(32, H_DIM / 128, E_NUM), 256>>>(x, dwn);

    combine_kernel<<<(T_TOK * H_DIM / 4 + 255) / 256, 256>>>(out);
    if (auxp) aux_kernel<<<1, 32>>>(auxp);
}

// round 3
// speedup vs baseline: 2.2818x; 2.2818x over previous
#include <cuda_runtime.h>
#include <cuda_bf16.h>
#include <math.h>
#include <stdint.h>

// Problem constants
#define T_TOK 4096
#define H_DIM 2048
#define E_NUM 8
#define I_DIM 768
#define KSEL  2
#define N1    (2*I_DIM)
#define ROWS_TOTAL (T_TOK*KSEL)
#define AUX_COEF 0.001f

// ---------------- scratch ----------------
__device__ uint32_t g_inter2[(size_t)ROWS_TOTAL * I_DIM]; // packed bf16 hi(lo16)/lo(hi16)
__device__ float g_y[(size_t)ROWS_TOTAL * H_DIM];
__device__ int   g_sel[ROWS_TOTAL];
__device__ float g_wt[ROWS_TOTAL];
__device__ int   g_counts[E_NUM];
__device__ int   g_ofs[E_NUM];
__device__ int   g_cursor[E_NUM];
__device__ int   g_rows_tok[ROWS_TOTAL];
__device__ int   g_rows_slot[ROWS_TOTAL];
__device__ float g_rows_w[ROWS_TOTAL];
__device__ float g_prob_sum[E_NUM];

// ---------------- helpers ----------------
__device__ __forceinline__ uint32_t smem_u32(const void* p) {
    uint32_t a;
    asm("{ .reg .u64 t; cvta.to.shared.u64 t, %1; cvt.u32.u64 %0, t; }" : "=r"(a) : "l"(p));
    return a;
}
__device__ __forceinline__ void ldsm_x4(uint32_t* r, uint32_t addr) {
    asm volatile("ldmatrix.sync.aligned.m8n8.x4.shared.b16 {%0,%1,%2,%3}, [%4];"
        : "=r"(r[0]), "=r"(r[1]), "=r"(r[2]), "=r"(r[3]) : "r"(addr));
}
__device__ __forceinline__ void mma16816(float* c, const uint32_t* a, const uint32_t* b) {
    asm volatile("mma.sync.aligned.m16n8k16.row.col.f32.bf16.bf16.f32 "
        "{%0,%1,%2,%3}, {%4,%5,%6,%7}, {%8,%9}, {%0,%1,%2,%3};"
        : "+f"(c[0]), "+f"(c[1]), "+f"(c[2]), "+f"(c[3])
        : "r"(a[0]), "r"(a[1]), "r"(a[2]), "r"(a[3]), "r"(b[0]), "r"(b[1]));
}
__device__ __forceinline__ uint16_t bf_bits(__nv_bfloat16 h) {
    return *reinterpret_cast<unsigned short*>(&h);
}
__device__ __forceinline__ void split4(float4 v, uint2& h, uint2& l) {
    __nv_bfloat162 hxy = __floats2bfloat162_rn(v.x, v.y);
    __nv_bfloat162 hzw = __floats2bfloat162_rn(v.z, v.w);
    float2 fxy = __bfloat1622float2(hxy);
    float2 fzw = __bfloat1622float2(hzw);
    __nv_bfloat162 lxy = __floats2bfloat162_rn(v.x - fxy.x, v.y - fxy.y);
    __nv_bfloat162 lzw = __floats2bfloat162_rn(v.z - fzw.x, v.w - fzw.y);
    h.x = *reinterpret_cast<uint32_t*>(&hxy); h.y = *reinterpret_cast<uint32_t*>(&hzw);
    l.x = *reinterpret_cast<uint32_t*>(&lxy); l.y = *reinterpret_cast<uint32_t*>(&lzw);
}

// ---------------- init / router / offsets / scatter (validated R1) ---------
__global__ void init_kernel() {
    int i = threadIdx.x;
    if (i < E_NUM) { g_counts[i] = 0; g_prob_sum[i] = 0.f; }
}

__global__ void router_kernel(const float* __restrict__ x,
                              const float* __restrict__ gw,
                              float* __restrict__ logits_out) {
    const int t = blockIdx.x;
    const float* xr = x + (size_t)t * H_DIM;
    float acc[E_NUM];
#pragma unroll
    for (int e = 0; e < E_NUM; e++) acc[e] = 0.f;
    for (int h = threadIdx.x; h < H_DIM; h += blockDim.x) {
        float xv = xr[h];
        const float4 g0 = *(const float4*)(gw + (size_t)h * E_NUM);
        const float4 g1 = *(const float4*)(gw + (size_t)h * E_NUM + 4);
        acc[0] += xv * g0.x; acc[1] += xv * g0.y; acc[2] += xv * g0.z; acc[3] += xv * g0.w;
        acc[4] += xv * g1.x; acc[5] += xv * g1.y; acc[6] += xv * g1.z; acc[7] += xv * g1.w;
    }
#pragma unroll
    for (int e = 0; e < E_NUM; e++)
#pragma unroll
        for (int o = 16; o; o >>= 1) acc[e] += __shfl_xor_sync(0xffffffffu, acc[e], o);
    __shared__ float red[E_NUM][8];
    int warp = threadIdx.x >> 5, lane = threadIdx.x & 31;
    if (lane == 0)
#pragma unroll
        for (int e = 0; e < E_NUM; e++) red[e][warp] = acc[e];
    __syncthreads();
    if (threadIdx.x == 0) {
        float lg[E_NUM];
#pragma unroll
        for (int e = 0; e < E_NUM; e++) {
            float s = 0.f;
#pragma unroll
            for (int w = 0; w < 8; w++) s += red[e][w];
            lg[e] = s;
        }
        if (logits_out)
#pragma unroll
            for (int e = 0; e < E_NUM; e++) logits_out[(size_t)t * E_NUM + e] = lg[e];
        float mx = lg[0];
#pragma unroll
        for (int e = 1; e < E_NUM; e++) mx = fmaxf(mx, lg[e]);
        float p[E_NUM], s = 0.f;
#pragma unroll
        for (int e = 0; e < E_NUM; e++) { p[e] = expf(lg[e] - mx); s += p[e]; }
        float inv = 1.f / s;
#pragma unroll
        for (int e = 0; e < E_NUM; e++) { p[e] *= inv; atomicAdd(&g_prob_sum[e], p[e]); }
        bool used[E_NUM];
#pragma unroll
        for (int e = 0; e < E_NUM; e++) used[e] = false;
        int si[KSEL]; float sp[KSEL]; float wsum = 0.f;
#pragma unroll
        for (int k = 0; k < KSEL; k++) {
            int bi = -1; float bv = -1.f;
#pragma unroll
            for (int e = 0; e < E_NUM; e++)
                if (!used[e] && p[e] > bv) { bv = p[e]; bi = e; }
            used[bi] = true; si[k] = bi; sp[k] = bv; wsum += bv;
        }
        float winv = 1.f / wsum;
#pragma unroll
        for (int k = 0; k < KSEL; k++) {
            g_sel[t * KSEL + k] = si[k];
            g_wt[t * KSEL + k]  = sp[k] * winv;
            atomicAdd(&g_counts[si[k]], 1);
        }
    }
}

__global__ void offsets_kernel() {
    if (threadIdx.x == 0) {
        int run = 0;
        for (int e = 0; e < E_NUM; e++) { g_ofs[e] = run; g_cursor[e] = run; run += g_counts[e]; }
    }
}

__global__ void scatter_kernel() {
    int i = blockIdx.x * blockDim.x + threadIdx.x;
    if (i >= ROWS_TOTAL) return;
    int e = g_sel[i];
    int p = atomicAdd(&g_cursor[e], 1);
    g_rows_tok[p]  = i / KSEL;
    g_rows_slot[p] = i % KSEL;
    g_rows_w[p]    = g_wt[i];
}

// ---------------- HMMA expert GEMM (bf16 3-pass split) ----------------------
// CTA tile 128x128, K-chunk 32. smem arrays stride 40 bf16 (conflict-free).
// MODE 1: A = gathered x rows (fp32), B = gate_up (rows: 64 gate + 64 up of
//         the same inter columns). Epilogue: silu fuse -> g_inter2 packed.
// MODE 2: A = g_inter2 (packed bf16 hi/lo), B = down_proj. Epilogue: *= weight,
//         scatter fp32 rows into g_y[(tok*2+slot)].
#define SROW 40
#define ARR_BYTES (128 * SROW * 2)     // 10240
#define STG_BYTES (4 * ARR_BYTES)      // 40960
#define OFF_AHI 0
#define OFF_ALO ARR_BYTES
#define OFF_BHI (2 * ARR_BYTES)
#define OFF_BLO (3 * ARR_BYTES)
#define SMEM_TOT (2 * STG_BYTES)       // 81920

template<int KDIM, int MODE>
__global__ void __launch_bounds__(256)
moe_gemm_mma(const float* __restrict__ x, const float* __restrict__ w) {
    constexpr int NCH  = KDIM / 32;
    constexpr int NDIM = (MODE == 1) ? N1 : H_DIM;
    const int e   = blockIdx.z;
    const int cnt = g_counts[e];
    const int m0  = blockIdx.x * 128;
    if (m0 >= cnt) return;
    const int nb  = blockIdx.y;
    const int ofs = g_ofs[e];

    extern __shared__ char smem[];
    const uint32_t sb = smem_u32(smem);

    const int tid  = threadIdx.x;
    const int wid  = tid >> 5;
    const int lane = tid & 31;
    const int wm   = wid & 1;     // m64 half
    const int wn   = wid >> 1;    // n32 quarter

    // ---- per-thread fixed source pointers for the loader ----
    const float* arow_f[4];
    const uint32_t* arow_p[4];
    const float* brow[4];
    int aq[4], bq[4];
#pragma unroll
    for (int i = 0; i < 4; i++) {
        int ei = i * 256 + tid;
        int r = ei >> 3, q = ei & 7;
        aq[i] = q; bq[i] = q;
        int lm = m0 + r; if (lm > cnt - 1) lm = cnt - 1;
        if (MODE == 1) arow_f[i] = x + (size_t)__ldg(&g_rows_tok[ofs + lm]) * H_DIM;
        else           arow_p[i] = g_inter2 + (size_t)(ofs + lm) * I_DIM;
        int gn;
        if (MODE == 1) gn = (r < 64) ? (nb * 64 + r) : (I_DIM + nb * 64 + (r - 64));
        else           gn = nb * 128 + r;
        brow[i] = w + ((size_t)e * NDIM + gn) * KDIM;
    }
    // smem row offsets for stores (fixed per thread)
    int srow_off[4];
#pragma unroll
    for (int i = 0; i < 4; i++) {
        int ei = i * 256 + tid;
        int r = ei >> 3, q = ei & 7;
        srow_off[i] = (r * SROW + q * 4) * 2;   // byte offset within array
    }

    float4 av[4]; uint4 ap[4]; float4 bv[4];

    auto load_chunk = [&](int c) {
        const int kt = c * 32;
#pragma unroll
        for (int i = 0; i < 4; i++) {
            if (MODE == 1) av[i] = __ldg((const float4*)(arow_f[i] + kt + aq[i] * 4));
            else           ap[i] = __ldg((const uint4*)(arow_p[i] + kt + aq[i] * 4));
            bv[i] = __ldg((const float4*)(brow[i] + kt + bq[i] * 4));
        }
    };
    auto sts_chunk = [&](int s) {
        char* st = smem + s * STG_BYTES;
#pragma unroll
        for (int i = 0; i < 4; i++) {
            uint2 h, l;
            if (MODE == 1) {
                split4(av[i], h, l);
            } else {
                uint32_t e0 = ap[i].x, e1 = ap[i].y, e2 = ap[i].z, e3 = ap[i].w;
                h.x = (e0 & 0xffffu) | (e1 << 16);
                h.y = (e2 & 0xffffu) | (e3 << 16);
                l.x = (e0 >> 16) | (e1 & 0xffff0000u);
                l.y = (e2 >> 16) | (e3 & 0xffff0000u);
            }
            *(uint2*)(st + OFF_AHI + srow_off[i]) = h;
            *(uint2*)(st + OFF_ALO + srow_off[i]) = l;
            split4(bv[i], h, l);
            *(uint2*)(st + OFF_BHI + srow_off[i]) = h;
            *(uint2*)(st + OFF_BLO + srow_off[i]) = l;
        }
    };

    // ldmatrix per-thread base offsets (bytes, within array)
    const uint32_t a_base = ((wm * 64 + (lane & 15)) * SROW + (lane >> 4) * 8) * 2;
    const uint32_t b_base = ((wn * 32 + ((lane >> 4) << 3) + (lane & 7)) * SROW + ((lane >> 3) & 1) * 8) * 2;

    float acc[4][4][4];
#pragma unroll
    for (int i = 0; i < 4; i++)
#pragma unroll
        for (int j = 0; j < 4; j++)
#pragma unroll
            for (int k = 0; k < 4; k++) acc[i][j][k] = 0.f;

    load_chunk(0);
    sts_chunk(0);
    __syncthreads();

    for (int c = 0; c < NCH; c++) {
        const int s = c & 1;
        if (c + 1 < NCH) load_chunk(c + 1);

        const uint32_t stg = sb + s * STG_BYTES;
#pragma unroll
        for (int kk = 0; kk < 2; kk++) {
            const uint32_t koff = kk * 16 * 2;
            uint32_t af[4][4], bh[2][4], bl[2][4];
#pragma unroll
            for (int im = 0; im < 4; im++)
                ldsm_x4(af[im], stg + OFF_AHI + a_base + im * (16 * SROW * 2) + koff);
#pragma unroll
            for (int g = 0; g < 2; g++) {
                ldsm_x4(bh[g], stg + OFF_BHI + b_base + g * (16 * SROW * 2) + koff);
                ldsm_x4(bl[g], stg + OFF_BLO + b_base + g * (16 * SROW * 2) + koff);
            }
            // pass 1: A_hi * B_hi ; pass 2: A_hi * B_lo
#pragma unroll
            for (int im = 0; im < 4; im++)
#pragma unroll
                for (int g = 0; g < 2; g++) {
                    mma16816(acc[im][g * 2 + 0], af[im], &bh[g][0]);
                    mma16816(acc[im][g * 2 + 1], af[im], &bh[g][2]);
                    mma16816(acc[im][g * 2 + 0], af[im], &bl[g][0]);
                    mma16816(acc[im][g * 2 + 1], af[im], &bl[g][2]);
                }
            // pass 3: A_lo * B_hi (reuse af regs)
#pragma unroll
            for (int im = 0; im < 4; im++)
                ldsm_x4(af[im], stg + OFF_ALO + a_base + im * (16 * SROW * 2) + koff);
#pragma unroll
            for (int im = 0; im < 4; im++)
#pragma unroll
                for (int g = 0; g < 2; g++) {
                    mma16816(acc[im][g * 2 + 0], af[im], &bh[g][0]);
                    mma16816(acc[im][g * 2 + 1], af[im], &bh[g][2]);
                }
        }
        __syncthreads();
        if (c + 1 < NCH) {
            sts_chunk(s ^ 1);
            __syncthreads();
        }
    }

    // ---------------- epilogue ----------------
    if (MODE == 1) {
        float* Cs = (float*)smem;   // 128x128 fp32 = 64KB (aliases stages)
#pragma unroll
        for (int im = 0; im < 4; im++)
#pragma unroll
            for (int jn = 0; jn < 4; jn++) {
                int row = wm * 64 + im * 16 + (lane >> 2);
                int col = wn * 32 + jn * 8 + (lane & 3) * 2;
                *(float2*)&Cs[row * 128 + col]       = make_float2(acc[im][jn][0], acc[im][jn][1]);
                *(float2*)&Cs[(row + 8) * 128 + col] = make_float2(acc[im][jn][2], acc[im][jn][3]);
            }
        __syncthreads();
        int r = tid >> 1, half = tid & 1;
        if (m0 + r < cnt) {
            int grow = ofs + m0 + r;
            uint32_t outw[32];
#pragma unroll
            for (int j = 0; j < 32; j++) {
                float g = Cs[r * 128 + half * 32 + j];
                float u = Cs[r * 128 + 64 + half * 32 + j];
                float vi = (g / (1.f + __expf(-g))) * u;
                __nv_bfloat16 hh = __float2bfloat16(vi);
                __nv_bfloat16 ll = __float2bfloat16(vi - __bfloat162float(hh));
                outw[j] = (uint32_t)bf_bits(hh) | ((uint32_t)bf_bits(ll) << 16);
            }
            uint32_t* dst = g_inter2 + (size_t)grow * I_DIM + nb * 64 + half * 32;
#pragma unroll
            for (int j = 0; j < 8; j++) ((uint4*)dst)[j] = ((uint4*)outw)[j];
        }
    } else {
#pragma unroll
        for (int im = 0; im < 4; im++) {
#pragma unroll
            for (int half = 0; half < 2; half++) {
                int r = m0 + wm * 64 + im * 16 + (lane >> 2) + half * 8;
                if (r < cnt) {
                    int gr = ofs + r;
                    float wgt = g_rows_w[gr];
                    int t = g_rows_tok[gr], sl = g_rows_slot[gr];
                    float* base = g_y + ((size_t)t * KSEL + sl) * H_DIM + nb * 128 + wn * 32;
#pragma unroll
                    for (int jn = 0; jn < 4; jn++) {
                        int col = jn * 8 + (lane & 3) * 2;
                        float2 v = make_float2(acc[im][jn][half * 2] * wgt,
                                               acc[im][jn][half * 2 + 1] * wgt);
                        *(float2*)(base + col) = v;
                    }
                }
            }
        }
    }
}

// ---------------- combine / aux ----------------
__global__ void combine_kernel(float* __restrict__ out) {
    int i = blockIdx.x * blockDim.x + threadIdx.x;
    if (i >= T_TOK * H_DIM / 4) return;
    const int nv = H_DIM / 4;
    int t = i / nv, n = i - t * nv;
    const float4* y = (const float4*)g_y;
    float4 a = y[((size_t)t * KSEL + 0) * nv + n];
    float4 b = y[((size_t)t * KSEL + 1) * nv + n];
    a.x += b.x; a.y += b.y; a.z += b.z; a.w += b.w;
    ((float4*)out)[i] = a;
}

__global__ void aux_kernel(float* __restrict__ aux_out) {
    if (threadIdx.x == 0) {
        float aux = 0.f;
        float invT = 1.f / (float)T_TOK;
        for (int e = 0; e < E_NUM; e++)
            aux += (g_prob_sum[e] * invT) * ((float)g_counts[e] * invT);
        aux_out[0] = aux * (float)E_NUM * AUX_COEF;
    }
}

// ---------------- launch ----------------
extern "C" void kernel_launch(void* const* d_in, const int* in_sizes, int n_in,
                              void* d_out, int out_size) {
    const float* x   = (const float*)d_in[0];
    const float* gw  = (const float*)d_in[1];
    const float* gup = (const float*)d_in[2];
    const float* dwn = (const float*)d_in[3];
    float* out = (float*)d_out;

    const long long need_logits = (long long)T_TOK * H_DIM + (long long)T_TOK * E_NUM;
    float* logits = ((long long)out_size >= need_logits) ? out + (size_t)T_TOK * H_DIM : nullptr;
    float* auxp   = ((long long)out_size >= need_logits + 1) ? logits + (size_t)T_TOK * E_NUM : nullptr;

    cudaFuncSetAttribute(moe_gemm_mma<H_DIM, 1>, cudaFuncAttributeMaxDynamicSharedMemorySize, SMEM_TOT);
    cudaFuncSetAttribute(moe_gemm_mma<I_DIM, 2>, cudaFuncAttributeMaxDynamicSharedMemorySize, SMEM_TOT);

    init_kernel<<<1, 32>>>();
    router_kernel<<<T_TOK, 256>>>(x, gw, logits);
    offsets_kernel<<<1, 32>>>();
    scatter_kernel<<<(ROWS_TOTAL + 255) / 256, 256>>>();

    // GEMM1: (gathered x) @ gate_up^T, fused silu -> g_inter2 (packed bf16 hi/lo)
    moe_gemm_mma<H_DIM, 1><<<dim3(32, I_DIM / 64, E_NUM), 256, SMEM_TOT>>>(x, gup);
    // GEMM2: inter @ down^T, scaled, scattered -> g_y
    moe_gemm_mma<I_DIM, 2><<<dim3(32, H_DIM / 128, E_NUM), 256, SMEM_TOT>>>(x, dwn);

    combine_kernel<<<(T_TOK * H_DIM / 4 + 255) / 256, 256>>>(out);
    if (auxp) aux_kernel<<<1, 32>>>(auxp);
}